// round 5
// baseline (speedup 1.0000x reference)
#include <cuda_runtime.h>

// RLGate: B=4, T=2048, D=1024, E=8, K=2
// Split design: select kernel (logits+gumbel top2 -> g_sidx, per-CTA aux partial)
//               gather kernel (pure 96MB stream + aux reduce by CTA 0)

#define BB      4
#define TT      2048
#define DD      1024
#define EE      8
#define NTOK    (BB * TT)          // 8192
#define TPB_TOK 8                   // tokens per CTA (select)
#define NCTA_S  (NTOK / TPB_TOK)    // 1024
#define GTOK    8                   // tokens per CTA (gather)
#define NCTA_G  (NTOK / GTOK)       // 1024
#define EPSF    1e-9f

__device__ int2  g_sidx[NTOK];
__device__ float g_contrib[NCTA_S];

// ---------------------------------------------------------------- select ----
__global__ __launch_bounds__(256) void rlgate_select(
    const float* __restrict__ x,
    const float* __restrict__ rewards,
    const float* __restrict__ W,
    const float* __restrict__ bias,
    const float* __restrict__ baseline,
    const float* __restrict__ noise_u)
{
    const int tid  = threadIdx.x;
    const int lane = tid & 31;
    const int warp = tid >> 5;
    const int tokBase = blockIdx.x * TPB_TOK;

    __shared__ __align__(16) float Wt[EE][1032];
    __shared__ float part[TPB_TOK][64];
    __shared__ float logit_s[TPB_TOK][EE];

    // stage W -> smem transposed (coalesced gmem; L2-resident after wave 1)
    const float4* W4 = reinterpret_cast<const float4*>(W);   // 2048 float4
    #pragma unroll
    for (int k = 0; k < 8; k++) {
        int idx = tid + 256 * k;
        float4 wv = W4[idx];
        int d  = idx >> 1;
        int e0 = (idx & 1) * 4;
        Wt[e0 + 0][d] = wv.x;
        Wt[e0 + 1][d] = wv.y;
        Wt[e0 + 2][d] = wv.z;
        Wt[e0 + 3][d] = wv.w;
    }
    __syncthreads();

    float wr[EE][4];
    #pragma unroll
    for (int e = 0; e < EE; e++) {
        float4 t4 = *reinterpret_cast<const float4*>(&Wt[e][4 * tid]);
        wr[e][0] = t4.x; wr[e][1] = t4.y; wr[e][2] = t4.z; wr[e][3] = t4.w;
    }

    // logits partials, x loads front-batched
    const float4* X4 = reinterpret_cast<const float4*>(x);
    float4 xv[TPB_TOK];
    #pragma unroll
    for (int t = 0; t < TPB_TOK; t++)
        xv[t] = X4[(size_t)(tokBase + t) * (DD / 4) + tid];

    #pragma unroll
    for (int t = 0; t < TPB_TOK; t++) {
        float v[EE];
        #pragma unroll
        for (int e = 0; e < EE; e++) {
            v[e] = xv[t].x * wr[e][0];
            v[e] = fmaf(xv[t].y, wr[e][1], v[e]);
            v[e] = fmaf(xv[t].z, wr[e][2], v[e]);
            v[e] = fmaf(xv[t].w, wr[e][3], v[e]);
        }
        #pragma unroll
        for (int e = 0; e < EE; e++) v[e] += __shfl_xor_sync(0xFFFFFFFFu, v[e], 16);
        if (lane & 16) { v[0] = v[4]; v[1] = v[5]; v[2] = v[6]; v[3] = v[7]; }
        #pragma unroll
        for (int i = 0; i < 4; i++)  v[i] += __shfl_xor_sync(0xFFFFFFFFu, v[i], 8);
        if (lane & 8)  { v[0] = v[2]; v[1] = v[3]; }
        #pragma unroll
        for (int i = 0; i < 2; i++)  v[i] += __shfl_xor_sync(0xFFFFFFFFu, v[i], 4);
        if (lane & 4)  { v[0] = v[1]; }
        v[0] += __shfl_xor_sync(0xFFFFFFFFu, v[0], 2);
        v[0] += __shfl_xor_sync(0xFFFFFFFFu, v[0], 1);
        if ((lane & 3) == 0) part[t][warp * 8 + (lane >> 2)] = v[0];
    }
    __syncthreads();

    // cross-warp sum -> logits
    if (tid < TPB_TOK * EE) {
        const int t = tid >> 3, e = tid & 7;
        float s = bias[e];
        #pragma unroll
        for (int w = 0; w < 8; w++) s += part[t][w * 8 + e];
        logit_s[t][e] = s;
    }
    __syncthreads();

    // softmax + gumbel top-2 + aux (8 threads)
    float contrib = 0.0f;
    if (tid < TPB_TOK) {
        const int t = tid;
        const int tok = tokBase + t;
        float l[EE];
        #pragma unroll
        for (int e = 0; e < EE; e++) l[e] = logit_s[t][e];
        float mx = l[0];
        #pragma unroll
        for (int e = 1; e < EE; e++) mx = fmaxf(mx, l[e]);
        float p[EE], sum = 0.0f;
        #pragma unroll
        for (int e = 0; e < EE; e++) { p[e] = __expf(l[e] - mx); sum += p[e]; }
        const float inv = 1.0f / sum;

        float lp[EE], sc[EE];
        const float* nu = noise_u + (size_t)tok * EE;
        #pragma unroll
        for (int e = 0; e < EE; e++) {
            lp[e] = logf(p[e] * inv + EPSF);
            float u = nu[e] * (1.0f - 2e-7f) + 1e-7f;
            sc[e] = lp[e] - logf(-logf(u));
        }
        int i0 = 0;
        #pragma unroll
        for (int e = 1; e < EE; e++) if (sc[e] > sc[i0]) i0 = e;
        int i1 = (i0 == 0) ? 1 : 0;
        #pragma unroll
        for (int e = 0; e < EE; e++) if (e != i0 && sc[e] > sc[i1]) i1 = e;

        g_sidx[tok] = make_int2(i0, i1);

        const float adv = rewards[tok] - baseline[0];
        contrib = -(adv * (lp[i0] + lp[i1])) * (1.0f / (float)NTOK);
    }
    if (tid < 32) {
        #pragma unroll
        for (int off = 4; off > 0; off >>= 1)
            contrib += __shfl_down_sync(0xFFFFFFFFu, contrib, off);
        if (lane == 0) g_contrib[blockIdx.x] = contrib;
    }
}

// ---------------------------------------------------------------- gather ----
__global__ __launch_bounds__(256) void rlgate_gather(
    const float* __restrict__ eo,
    float* __restrict__ out)
{
    const int tid = threadIdx.x;
    const int tokBase = blockIdx.x * GTOK;

    // preload indices for all 8 tokens (broadcast within CTA, L1/L2 hits)
    int2 s[GTOK];
    #pragma unroll
    for (int g = 0; g < GTOK; g++) s[g] = g_sidx[tokBase + g];

    const float4* EO4 = reinterpret_cast<const float4*>(eo);
    float4* OUT4 = reinterpret_cast<float4*>(out);

    #pragma unroll
    for (int gb = 0; gb < GTOK; gb += 4) {
        float4 a[4], c[4];
        #pragma unroll
        for (int j = 0; j < 4; j++) {
            const int tok = tokBase + gb + j;
            const size_t base4 = (size_t)tok * (DD / 4) + tid;
            a[j] = EO4[(size_t)s[gb + j].x * NTOK * (DD / 4) + base4];
            c[j] = EO4[(size_t)s[gb + j].y * NTOK * (DD / 4) + base4];
        }
        #pragma unroll
        for (int j = 0; j < 4; j++) {
            const int tok = tokBase + gb + j;
            const size_t base4 = (size_t)tok * (DD / 4) + tid;
            float4 r;
            r.x = (a[j].x + c[j].x) * 0.5f;
            r.y = (a[j].y + c[j].y) * 0.5f;
            r.z = (a[j].z + c[j].z) * 0.5f;
            r.w = (a[j].w + c[j].w) * 0.5f;
            OUT4[base4] = r;
        }
    }

    // CTA 0 reduces the aux partials (deterministic order)
    if (blockIdx.x == 0) {
        float ssum = 0.0f;
        for (int k = tid; k < NCTA_S; k += 256) ssum += g_contrib[k];
        #pragma unroll
        for (int off = 16; off > 0; off >>= 1)
            ssum += __shfl_down_sync(0xFFFFFFFFu, ssum, off);
        __shared__ float red[8];
        if ((tid & 31) == 0) red[tid >> 5] = ssum;
        __syncthreads();
        if (tid == 0) {
            float t = 0.0f;
            #pragma unroll
            for (int w = 0; w < 8; w++) t += red[w];
            out[(size_t)NTOK * DD] = t;
        }
    }
}

extern "C" void kernel_launch(void* const* d_in, const int* in_sizes, int n_in,
                              void* d_out, int out_size) {
    const float* x        = (const float*)d_in[0];
    const float* eo       = (const float*)d_in[1];
    const float* rewards  = (const float*)d_in[2];
    const float* W        = (const float*)d_in[3];
    const float* bias     = (const float*)d_in[4];
    const float* baseline = (const float*)d_in[5];
    const float* noise_u  = (const float*)d_in[6];
    float* out = (float*)d_out;

    rlgate_select<<<NCTA_S, 256>>>(x, rewards, W, bias, baseline, noise_u);
    rlgate_gather<<<NCTA_G, 256>>>(eo, out);
}

// round 6
// speedup vs baseline: 1.1965x; 1.1965x over previous
#include <cuda_runtime.h>

// RLGate: B=4, T=2048, D=1024, E=8, K=2
// Fused single kernel. Aux loss via per-CTA partial + last-block reduction
// (atomic counter, self-resetting for graph replay determinism).

#define BB      4
#define TT      2048
#define DD      1024
#define EE      8
#define NTOK    (BB * TT)          // 8192
#define TPB_TOK 16                  // tokens per CTA
#define NCTA    (NTOK / TPB_TOK)    // 512
#define EPSF    1e-9f

__device__ float g_contrib[NCTA];
__device__ int   g_count = 0;

__global__ __launch_bounds__(256) void rlgate_kernel(
    const float* __restrict__ x,
    const float* __restrict__ eo,
    const float* __restrict__ rewards,
    const float* __restrict__ W,
    const float* __restrict__ bias,
    const float* __restrict__ baseline,
    const float* __restrict__ noise_u,
    float* __restrict__ out)
{
    const int tid  = threadIdx.x;
    const int lane = tid & 31;
    const int warp = tid >> 5;
    const int tokBase = blockIdx.x * TPB_TOK;

    __shared__ __align__(16) float Wt[EE][1032];        // transposed W, padded
    __shared__ float part[TPB_TOK][64];
    __shared__ float logit_s[TPB_TOK][EE];
    __shared__ int   sidx_s[TPB_TOK][2];

    // ---- Phase 0: stage W -> smem transposed (coalesced; keep L2-resident) ----
    const float4* W4 = reinterpret_cast<const float4*>(W);   // 2048 float4
    #pragma unroll
    for (int k = 0; k < 8; k++) {
        int idx = tid + 256 * k;
        float4 wv = W4[idx];
        int d  = idx >> 1;
        int e0 = (idx & 1) * 4;
        Wt[e0 + 0][d] = wv.x;
        Wt[e0 + 1][d] = wv.y;
        Wt[e0 + 2][d] = wv.z;
        Wt[e0 + 3][d] = wv.w;
    }
    __syncthreads();

    float wr[EE][4];
    #pragma unroll
    for (int e = 0; e < EE; e++) {
        float4 t4 = *reinterpret_cast<const float4*>(&Wt[e][4 * tid]);
        wr[e][0] = t4.x; wr[e][1] = t4.y; wr[e][2] = t4.z; wr[e][3] = t4.w;
    }

    // ---- Phase 1: logits partials; x loads batched 4 tokens, streaming ----
    const float4* X4 = reinterpret_cast<const float4*>(x);
    #pragma unroll
    for (int tb = 0; tb < TPB_TOK; tb += 4) {
        float4 xv[4];
        #pragma unroll
        for (int j = 0; j < 4; j++)
            xv[j] = __ldcs(&X4[(size_t)(tokBase + tb + j) * (DD / 4) + tid]);

        #pragma unroll
        for (int j = 0; j < 4; j++) {
            const int t = tb + j;
            float v[EE];
            #pragma unroll
            for (int e = 0; e < EE; e++) {
                v[e] = xv[j].x * wr[e][0];
                v[e] = fmaf(xv[j].y, wr[e][1], v[e]);
                v[e] = fmaf(xv[j].z, wr[e][2], v[e]);
                v[e] = fmaf(xv[j].w, wr[e][3], v[e]);
            }
            // 16-shuffle multi-value warp reduction
            #pragma unroll
            for (int e = 0; e < EE; e++) v[e] += __shfl_xor_sync(0xFFFFFFFFu, v[e], 16);
            if (lane & 16) { v[0] = v[4]; v[1] = v[5]; v[2] = v[6]; v[3] = v[7]; }
            #pragma unroll
            for (int i = 0; i < 4; i++)  v[i] += __shfl_xor_sync(0xFFFFFFFFu, v[i], 8);
            if (lane & 8)  { v[0] = v[2]; v[1] = v[3]; }
            #pragma unroll
            for (int i = 0; i < 2; i++)  v[i] += __shfl_xor_sync(0xFFFFFFFFu, v[i], 4);
            if (lane & 4)  { v[0] = v[1]; }
            v[0] += __shfl_xor_sync(0xFFFFFFFFu, v[0], 2);
            v[0] += __shfl_xor_sync(0xFFFFFFFFu, v[0], 1);
            if ((lane & 3) == 0) part[t][warp * 8 + (lane >> 2)] = v[0];
        }
    }
    __syncthreads();

    // ---- Phase 2a: cross-warp sum -> logits ----
    if (tid < TPB_TOK * EE) {
        const int t = tid >> 3, e = tid & 7;
        float s = bias[e];
        #pragma unroll
        for (int w = 0; w < 8; w++) s += part[t][w * 8 + e];
        logit_s[t][e] = s;
    }
    __syncthreads();

    // ---- Phase 2b: softmax + gumbel top-2 + aux partial (16 threads) ----
    float contrib = 0.0f;
    if (tid < TPB_TOK) {
        const int t = tid;
        const int tok = tokBase + t;
        float l[EE];
        #pragma unroll
        for (int e = 0; e < EE; e++) l[e] = logit_s[t][e];
        float mx = l[0];
        #pragma unroll
        for (int e = 1; e < EE; e++) mx = fmaxf(mx, l[e]);
        float p[EE], sum = 0.0f;
        #pragma unroll
        for (int e = 0; e < EE; e++) { p[e] = __expf(l[e] - mx); sum += p[e]; }
        const float inv = 1.0f / sum;

        float lp[EE], sc[EE];
        const float* nu = noise_u + (size_t)tok * EE;
        #pragma unroll
        for (int e = 0; e < EE; e++) {
            lp[e] = logf(p[e] * inv + EPSF);
            float u = nu[e] * (1.0f - 2e-7f) + 1e-7f;
            sc[e] = lp[e] - logf(-logf(u));
        }
        int i0 = 0;
        #pragma unroll
        for (int e = 1; e < EE; e++) if (sc[e] > sc[i0]) i0 = e;
        int i1 = (i0 == 0) ? 1 : 0;
        #pragma unroll
        for (int e = 0; e < EE; e++) if (e != i0 && sc[e] > sc[i1]) i1 = e;

        sidx_s[t][0] = i0;
        sidx_s[t][1] = i1;

        const float adv = rewards[tok] - baseline[0];
        contrib = -(adv * (lp[i0] + lp[i1])) * (1.0f / (float)NTOK);
    }
    // warp 0: reduce 16 partials, publish per-CTA value, last CTA finalizes
    bool isLast = false;
    if (warp == 0) {
        #pragma unroll
        for (int off = 8; off > 0; off >>= 1)
            contrib += __shfl_down_sync(0xFFFFFFFFu, contrib, off);
        if (lane == 0) {
            g_contrib[blockIdx.x] = contrib;
            __threadfence();
            isLast = (atomicAdd(&g_count, 1) == NCTA - 1);
        }
        isLast = __shfl_sync(0xFFFFFFFFu, isLast ? 1 : 0, 0) != 0;
    }
    __syncthreads();

    // ---- Phase 3: gather 2 expert rows/token, average, write (streaming) ----
    const float4* EO4 = reinterpret_cast<const float4*>(eo);
    float4* OUT4 = reinterpret_cast<float4*>(out);
    #pragma unroll
    for (int tb = 0; tb < TPB_TOK; tb += 4) {
        float4 a[4], c[4];
        #pragma unroll
        for (int j = 0; j < 4; j++) {
            const int tok = tokBase + tb + j;
            const size_t base4 = (size_t)tok * (DD / 4) + tid;
            a[j] = __ldcs(&EO4[(size_t)sidx_s[tb + j][0] * NTOK * (DD / 4) + base4]);
            c[j] = __ldcs(&EO4[(size_t)sidx_s[tb + j][1] * NTOK * (DD / 4) + base4]);
        }
        #pragma unroll
        for (int j = 0; j < 4; j++) {
            const int tok = tokBase + tb + j;
            const size_t base4 = (size_t)tok * (DD / 4) + tid;
            float4 r;
            r.x = (a[j].x + c[j].x) * 0.5f;
            r.y = (a[j].y + c[j].y) * 0.5f;
            r.z = (a[j].z + c[j].z) * 0.5f;
            r.w = (a[j].w + c[j].w) * 0.5f;
            __stcs(&OUT4[base4], r);
        }
    }

    // last CTA's warp 0: reduce all per-CTA aux partials (deterministic set)
    if (warp == 0 && isLast) {
        __threadfence();
        float ssum = 0.0f;
        #pragma unroll
        for (int k = 0; k < NCTA / 32; k++)
            ssum += g_contrib[lane + 32 * k];
        #pragma unroll
        for (int off = 16; off > 0; off >>= 1)
            ssum += __shfl_down_sync(0xFFFFFFFFu, ssum, off);
        if (lane == 0) {
            out[(size_t)NTOK * DD] = ssum;
            g_count = 0;                      // reset for next graph replay
        }
    }
}

extern "C" void kernel_launch(void* const* d_in, const int* in_sizes, int n_in,
                              void* d_out, int out_size) {
    const float* x        = (const float*)d_in[0];
    const float* eo       = (const float*)d_in[1];
    const float* rewards  = (const float*)d_in[2];
    const float* W        = (const float*)d_in[3];
    const float* bias     = (const float*)d_in[4];
    const float* baseline = (const float*)d_in[5];
    const float* noise_u  = (const float*)d_in[6];
    float* out = (float*)d_out;

    rlgate_kernel<<<NCTA, 256>>>(x, eo, rewards, W, bias, baseline, noise_u, out);
}

// round 7
// speedup vs baseline: 1.2088x; 1.0103x over previous
#include <cuda_runtime.h>

// RLGate: B=4, T=2048, D=1024, E=8, K=2
// Fused kernel; phase-2 (softmax+gumbel+top2) parallelized one thread per
// (token, expert) with 8-lane shuffle reductions. Aux loss via per-CTA
// partial + last-block reduction (self-resetting counter).

#define BB      4
#define TT      2048
#define DD      1024
#define EE      8
#define NTOK    (BB * TT)          // 8192
#define TPB_TOK 16                  // tokens per CTA
#define NCTA    (NTOK / TPB_TOK)    // 512
#define EPSF    1e-9f
#define FULLM   0xFFFFFFFFu

__device__ float g_contrib[NCTA];
__device__ int   g_count = 0;

__global__ __launch_bounds__(256) void rlgate_kernel(
    const float* __restrict__ x,
    const float* __restrict__ eo,
    const float* __restrict__ rewards,
    const float* __restrict__ W,
    const float* __restrict__ bias,
    const float* __restrict__ baseline,
    const float* __restrict__ noise_u,
    float* __restrict__ out)
{
    const int tid  = threadIdx.x;
    const int lane = tid & 31;
    const int warp = tid >> 5;
    const int tokBase = blockIdx.x * TPB_TOK;

    __shared__ __align__(16) float Wt[EE][1024];   // transposed W
    __shared__ float part[TPB_TOK][64];
    __shared__ float logit_s[TPB_TOK][EE];
    __shared__ int   sidx_s[TPB_TOK][2];
    __shared__ float contrib_s[TPB_TOK];

    // ---- Phase 0: stage W -> smem transposed ----
    const float4* W4 = reinterpret_cast<const float4*>(W);   // 2048 float4
    #pragma unroll
    for (int k = 0; k < 8; k++) {
        int idx = tid + 256 * k;
        float4 wv = W4[idx];
        int d  = idx >> 1;
        int e0 = (idx & 1) * 4;
        Wt[e0 + 0][d] = wv.x;
        Wt[e0 + 1][d] = wv.y;
        Wt[e0 + 2][d] = wv.z;
        Wt[e0 + 3][d] = wv.w;
    }
    __syncthreads();

    float wr[EE][4];
    #pragma unroll
    for (int e = 0; e < EE; e++) {
        float4 t4 = *reinterpret_cast<const float4*>(&Wt[e][4 * tid]);
        wr[e][0] = t4.x; wr[e][1] = t4.y; wr[e][2] = t4.z; wr[e][3] = t4.w;
    }

    // ---- Phase 1: logits partials; x loads batched 4 tokens ----
    const float4* X4 = reinterpret_cast<const float4*>(x);
    #pragma unroll
    for (int tb = 0; tb < TPB_TOK; tb += 4) {
        float4 xv[4];
        #pragma unroll
        for (int j = 0; j < 4; j++)
            xv[j] = __ldcs(&X4[(size_t)(tokBase + tb + j) * (DD / 4) + tid]);

        #pragma unroll
        for (int j = 0; j < 4; j++) {
            const int t = tb + j;
            float v[EE];
            #pragma unroll
            for (int e = 0; e < EE; e++) {
                v[e] = xv[j].x * wr[e][0];
                v[e] = fmaf(xv[j].y, wr[e][1], v[e]);
                v[e] = fmaf(xv[j].z, wr[e][2], v[e]);
                v[e] = fmaf(xv[j].w, wr[e][3], v[e]);
            }
            #pragma unroll
            for (int e = 0; e < EE; e++) v[e] += __shfl_xor_sync(FULLM, v[e], 16);
            if (lane & 16) { v[0] = v[4]; v[1] = v[5]; v[2] = v[6]; v[3] = v[7]; }
            #pragma unroll
            for (int i = 0; i < 4; i++)  v[i] += __shfl_xor_sync(FULLM, v[i], 8);
            if (lane & 8)  { v[0] = v[2]; v[1] = v[3]; }
            #pragma unroll
            for (int i = 0; i < 2; i++)  v[i] += __shfl_xor_sync(FULLM, v[i], 4);
            if (lane & 4)  { v[0] = v[1]; }
            v[0] += __shfl_xor_sync(FULLM, v[0], 2);
            v[0] += __shfl_xor_sync(FULLM, v[0], 1);
            if ((lane & 3) == 0) part[t][warp * 8 + (lane >> 2)] = v[0];
        }
    }
    __syncthreads();

    // ---- Phase 2a: cross-warp sum -> logits (128 threads) ----
    if (tid < TPB_TOK * EE) {
        const int t = tid >> 3, e = tid & 7;
        float s = bias[e];
        #pragma unroll
        for (int w = 0; w < 8; w++) s += part[t][w * 8 + e];
        logit_s[t][e] = s;
    }
    __syncthreads();

    // ---- Phase 2b: one thread per (token, expert); 8-lane shuffle groups ----
    if (tid < TPB_TOK * EE) {
        const int t = tid >> 3, e = tid & 7;
        const int tok = tokBase + t;
        const float l = logit_s[t][e];

        // group (8-lane) max and sum
        float mx = l;
        #pragma unroll
        for (int off = 4; off > 0; off >>= 1)
            mx = fmaxf(mx, __shfl_xor_sync(FULLM, mx, off));
        float p = __expf(l - mx);
        float ps = p;
        #pragma unroll
        for (int off = 4; off > 0; off >>= 1)
            ps += __shfl_xor_sync(FULLM, ps, off);

        const float lp = logf(p / ps + EPSF);
        const float u  = noise_u[(size_t)tok * EE + e] * (1.0f - 2e-7f) + 1e-7f;
        const float sc = lp - logf(-logf(u));

        // butterfly top-2 carrying (m1,i1,m2,i2); strict '>' / lowest index
        float m1 = sc, m2 = -__int_as_float(0x7F800000);  // -inf
        int   i1 = e,  i2 = 8;
        #pragma unroll
        for (int off = 4; off > 0; off >>= 1) {
            float om1 = __shfl_xor_sync(FULLM, m1, off);
            int   oi1 = __shfl_xor_sync(FULLM, i1, off);
            float om2 = __shfl_xor_sync(FULLM, m2, off);
            int   oi2 = __shfl_xor_sync(FULLM, i2, off);
            const bool aFirst = (m1 > om1) || (m1 == om1 && i1 < oi1);
            float n1, n2; int ni1, ni2;
            if (aFirst) {
                n1 = m1; ni1 = i1;
                const bool s = (m2 > om1) || (m2 == om1 && i2 < oi1);
                n2 = s ? m2 : om1; ni2 = s ? i2 : oi1;
            } else {
                n1 = om1; ni1 = oi1;
                const bool s = (om2 > m1) || (om2 == m1 && oi2 < i1);
                n2 = s ? om2 : m1; ni2 = s ? oi2 : i1;
            }
            m1 = n1; i1 = ni1; m2 = n2; i2 = ni2;
        }

        // fetch selected log-probs from group lanes (all lanes execute)
        const int gbase = lane & ~7;
        const float lp0 = __shfl_sync(FULLM, lp, gbase + i1);
        const float lp1 = __shfl_sync(FULLM, lp, gbase + i2);

        if (e == 0) {
            sidx_s[t][0] = i1;
            sidx_s[t][1] = i2;
            const float adv = rewards[tok] - baseline[0];
            contrib_s[t] = -(adv * (lp0 + lp1)) * (1.0f / (float)NTOK);
        }
    }
    __syncthreads();

    // warp 0: publish per-CTA aux partial, grab last-CTA ticket
    bool isLast = false;
    if (warp == 0) {
        float c = (lane < TPB_TOK) ? contrib_s[lane] : 0.0f;
        #pragma unroll
        for (int off = 8; off > 0; off >>= 1)
            c += __shfl_xor_sync(FULLM, c, off);
        if (lane == 0) {
            g_contrib[blockIdx.x] = c;
            __threadfence();
            isLast = (atomicAdd(&g_count, 1) == NCTA - 1);
        }
        isLast = __shfl_sync(FULLM, isLast ? 1 : 0, 0) != 0;
    }

    // ---- Phase 3: gather 2 expert rows/token, average, write ----
    const float4* EO4 = reinterpret_cast<const float4*>(eo);
    float4* OUT4 = reinterpret_cast<float4*>(out);
    #pragma unroll
    for (int tb = 0; tb < TPB_TOK; tb += 4) {
        float4 a[4], c4[4];
        #pragma unroll
        for (int j = 0; j < 4; j++) {
            const int tok = tokBase + tb + j;
            const size_t base4 = (size_t)tok * (DD / 4) + tid;
            a[j]  = __ldcs(&EO4[(size_t)sidx_s[tb + j][0] * NTOK * (DD / 4) + base4]);
            c4[j] = __ldcs(&EO4[(size_t)sidx_s[tb + j][1] * NTOK * (DD / 4) + base4]);
        }
        #pragma unroll
        for (int j = 0; j < 4; j++) {
            const int tok = tokBase + tb + j;
            const size_t base4 = (size_t)tok * (DD / 4) + tid;
            float4 r;
            r.x = (a[j].x + c4[j].x) * 0.5f;
            r.y = (a[j].y + c4[j].y) * 0.5f;
            r.z = (a[j].z + c4[j].z) * 0.5f;
            r.w = (a[j].w + c4[j].w) * 0.5f;
            __stcs(&OUT4[base4], r);
        }
    }

    // last CTA: reduce all per-CTA aux partials (deterministic set)
    if (warp == 0 && isLast) {
        __threadfence();
        float ssum = 0.0f;
        #pragma unroll
        for (int k = 0; k < NCTA / 32; k++)
            ssum += g_contrib[lane + 32 * k];
        #pragma unroll
        for (int off = 16; off > 0; off >>= 1)
            ssum += __shfl_down_sync(FULLM, ssum, off);
        if (lane == 0) {
            out[(size_t)NTOK * DD] = ssum;
            g_count = 0;                      // reset for next graph replay
        }
    }
}

extern "C" void kernel_launch(void* const* d_in, const int* in_sizes, int n_in,
                              void* d_out, int out_size) {
    const float* x        = (const float*)d_in[0];
    const float* eo       = (const float*)d_in[1];
    const float* rewards  = (const float*)d_in[2];
    const float* W        = (const float*)d_in[3];
    const float* bias     = (const float*)d_in[4];
    const float* baseline = (const float*)d_in[5];
    const float* noise_u  = (const float*)d_in[6];
    float* out = (float*)d_out;

    rlgate_kernel<<<NCTA, 256>>>(x, eo, rewards, W, bias, baseline, noise_u, out);
}